// round 3
// baseline (speedup 1.0000x reference)
#include <cuda_runtime.h>
#include <math_constants.h>
#include <cstdint>

#define S_LEN 1500
#define BATCHN 2
#define NH 8
#define DM 16
#define DFF 128
#define NROWS (BATCHN * S_LEN)          // 3000
#define XELEMS (NROWS * DM)             // 48000
#define QPB 60                          // queries per block (4 warps x 15)
#define YBLK 25                         // 25*60 = 1500 exactly

// Scratch (no allocations allowed)
__device__ float g_x[XELEMS];
__device__ float g_q[XELEMS];           // [B,H,S,2]
__device__ float g_k[XELEMS];
__device__ float g_v[XELEMS];
__device__ float g_ctx[XELEMS];

__device__ __forceinline__ uint32_t smem_u32(const void* p) {
    uint32_t a;
    asm("{ .reg .u64 t; cvta.to.shared.u64 t, %1; cvt.u32.u64 %0, t; }"
        : "=r"(a) : "l"(p));
    return a;
}

// ---------------------------------------------------------------------------
// embed + layer-0 qkv: 32 rows per 512-thread block
__global__ void __launch_bounds__(512) embed_kernel(
    const float* __restrict__ enc, const float* __restrict__ srcw,
    const float* __restrict__ srcb, const float* __restrict__ Wq,
    const float* __restrict__ Wk, const float* __restrict__ Wv)
{
    __shared__ float swq[256], swk[256], swv[256];
    int tid = threadIdx.x;
    if (tid < 256) { swq[tid] = Wq[tid]; swk[tid] = Wk[tid]; swv[tid] = Wv[tid]; }

    int r = tid >> 4, d = tid & 15;
    int grow = blockIdx.x * 32 + r;          // = b*1500 + s
    int lane = tid & 31, base = lane & 16;
    float xv = 0.f;
    if (grow < NROWS) {
        int s = grow % S_LEN;
        const float c = -0.57564627324851148f;   // -ln(10000)/16
        float dv = __expf((float)(d & ~1) * c);
        float ph = (float)s * dv;
        float pe = (d & 1) ? cosf(ph) : sinf(ph);
        xv = enc[grow] * srcw[d] + srcb[d] + pe;
        g_x[grow * DM + d] = xv;
    }
    __syncthreads();

    float xk[16];
#pragma unroll
    for (int k = 0; k < 16; k++) xk[k] = __shfl_sync(0xffffffffu, xv, base + k);
    if (grow < NROWS) {
        float q = 0.f, kk = 0.f, vv = 0.f;
#pragma unroll
        for (int m = 0; m < 16; m++) {
            q  = fmaf(xk[m], swq[m * 16 + d], q);
            kk = fmaf(xk[m], swk[m * 16 + d], kk);
            vv = fmaf(xk[m], swv[m * 16 + d], vv);
        }
        int b = grow / S_LEN, s = grow - b * S_LEN;
        int h = d >> 1, dk = d & 1;
        int o = ((b * NH + h) * S_LEN + s) * 2 + dk;
        g_q[o] = q; g_k[o] = kk; g_v[o] = vv;
    }
}

// ---------------------------------------------------------------------------
// attention: warp-per-query single pass; exp in regs; scaled row staged in
// SMEM then stored via cp.async.bulk (TMA bulk store) to dodge STG issue cost.
__global__ void __launch_bounds__(128) attn_kernel(float* __restrict__ attn_out)
{
    __shared__ float4 skv[S_LEN];                        // 24000B (k.x,k.y,v.x,v.y)
    __shared__ __align__(16) float stag[4][S_LEN];       // 24000B row buffers

    int bh = blockIdx.x;
    int tid = threadIdx.x;
    const float2* kp = ((const float2*)g_k) + bh * S_LEN;
    const float2* vp = ((const float2*)g_v) + bh * S_LEN;
    for (int i = tid; i < S_LEN; i += 128) {
        float2 kk = kp[i], vv = vp[i];
        skv[i] = make_float4(kk.x, kk.y, vv.x, vv.y);
    }
    __syncthreads();

    int warp = tid >> 5, lane = tid & 31;
    uint32_t sbuf = smem_u32(&stag[warp][0]);
    int b = bh >> 3, h = bh & 7;
    int qbase = blockIdx.y * QPB + warp * 15;
    const float scale = 0.70710678118654752f;   // 1/sqrt(2)

    for (int r = 0; r < 15; r++) {
        int q = qbase + r;
        float2 qv = ((const float2*)g_q)[bh * S_LEN + q];
        qv.x *= scale; qv.y *= scale;

        float4 e[12];
        float sum = 0.f, c0 = 0.f, c1 = 0.f;
#pragma unroll
        for (int i = 0; i < 12; i++) {
            int i4 = lane + 32 * i;              // covers keys 4*i4 .. 4*i4+3
            if (i4 < 375) {
                float4 kv0 = skv[4 * i4 + 0];
                float4 kv1 = skv[4 * i4 + 1];
                float4 kv2 = skv[4 * i4 + 2];
                float4 kv3 = skv[4 * i4 + 3];
                float4 A;
                A.x = __expf(qv.x * kv0.x + qv.y * kv0.y);
                A.y = __expf(qv.x * kv1.x + qv.y * kv1.y);
                A.z = __expf(qv.x * kv2.x + qv.y * kv2.y);
                A.w = __expf(qv.x * kv3.x + qv.y * kv3.y);
                sum += (A.x + A.y) + (A.z + A.w);
                c0 = fmaf(A.x, kv0.z, fmaf(A.y, kv1.z, fmaf(A.z, kv2.z, fmaf(A.w, kv3.z, c0))));
                c1 = fmaf(A.x, kv0.w, fmaf(A.y, kv1.w, fmaf(A.z, kv2.w, fmaf(A.w, kv3.w, c1))));
                e[i] = A;
            }
        }
#pragma unroll
        for (int o = 16; o; o >>= 1) {
            sum += __shfl_xor_sync(0xffffffffu, sum, o);
            c0  += __shfl_xor_sync(0xffffffffu, c0, o);
            c1  += __shfl_xor_sync(0xffffffffu, c1, o);
        }
        float rcp = 1.0f / sum;

        // buffer reuse: previous bulk store must have finished READING smem
        if (lane == 0)
            asm volatile("cp.async.bulk.wait_group.read 0;" ::: "memory");
        __syncwarp();

        float4* srow = (float4*)&stag[warp][0];
#pragma unroll
        for (int i = 0; i < 12; i++) {
            int i4 = lane + 32 * i;
            if (i4 < 375) {
                float4 A = e[i];
                A.x *= rcp; A.y *= rcp; A.z *= rcp; A.w *= rcp;
                srow[i4] = A;
            }
        }
        __syncwarp();

        if (lane == 0) {
            asm volatile("fence.proxy.async.shared::cta;" ::: "memory");
            float* gdst = attn_out + ((size_t)bh * S_LEN + q) * S_LEN;
            asm volatile(
                "cp.async.bulk.global.shared::cta.bulk_group [%0], [%1], %2;"
                :: "l"(gdst), "r"(sbuf), "r"((uint32_t)(S_LEN * 4)) : "memory");
            asm volatile("cp.async.bulk.commit_group;" ::: "memory");
            int basec = (b * S_LEN + q) * DM + h * 2;
            g_ctx[basec]     = c0 * rcp;
            g_ctx[basec + 1] = c1 * rcp;
        }
    }
    // pending bulk stores complete at kernel exit; global visibility guaranteed
    if (lane == 0)
        asm volatile("cp.async.bulk.wait_group 0;" ::: "memory");
}

// ---------------------------------------------------------------------------
// post: x=LN(ctx@Wo+x); x=LN(relu(x@W1)@W2+x); then next-layer qkv (fused).
__global__ void __launch_bounds__(512) post_kernel(
    const float* __restrict__ Wo, const float* __restrict__ W1,
    const float* __restrict__ W2, const float* __restrict__ Wqn,
    const float* __restrict__ Wkn, const float* __restrict__ Wvn,
    float* __restrict__ outx, int last)
{
    __shared__ float sw1[DM * DFF];
    __shared__ float sw2[DFF * DM];
    __shared__ float swo[256];
    __shared__ float swq[256], swk[256], swv[256];
    __shared__ float sh[32][DFF];

    int tid = threadIdx.x;
    if (tid < 256) swo[tid] = Wo[tid];
    for (int i = tid; i < DM * DFF; i += 512) { sw1[i] = W1[i]; sw2[i] = W2[i]; }
    if (!last && tid < 256) { swq[tid] = Wqn[tid]; swk[tid] = Wkn[tid]; swv[tid] = Wvn[tid]; }

    int r = tid >> 4, d = tid & 15;
    int grow = blockIdx.x * 32 + r;
    int lane = tid & 31, base = lane & 16;
    bool ok = grow < NROWS;
    float xv = ok ? g_x[grow * DM + d]   : 0.f;
    float cv = ok ? g_ctx[grow * DM + d] : 0.f;
    __syncthreads();

    float s1 = xv;
#pragma unroll
    for (int k = 0; k < 16; k++) {
        float ck = __shfl_sync(0xffffffffu, cv, base + k);
        s1 = fmaf(ck, swo[k * 16 + d], s1);
    }

    float mean = s1;
#pragma unroll
    for (int o = 8; o; o >>= 1) mean += __shfl_xor_sync(0xffffffffu, mean, o);
    mean *= (1.0f / 16.0f);
    float dv = s1 - mean;
    float var = dv * dv;
#pragma unroll
    for (int o = 8; o; o >>= 1) var += __shfl_xor_sync(0xffffffffu, var, o);
    var *= (1.0f / 16.0f);
    float t = dv * rsqrtf(var + 1e-5f);

    float tk[16];
#pragma unroll
    for (int k = 0; k < 16; k++) tk[k] = __shfl_sync(0xffffffffu, t, base + k);
#pragma unroll
    for (int i = 0; i < 8; i++) {
        int j = d + 16 * i;
        float hv = 0.f;
#pragma unroll
        for (int k = 0; k < 16; k++) hv = fmaf(tk[k], sw1[k * DFF + j], hv);
        sh[r][j] = fmaxf(hv, 0.f);
    }
    __syncthreads();

    float s2 = t;
#pragma unroll
    for (int j = 0; j < DFF; j++) s2 = fmaf(sh[r][j], sw2[j * 16 + d], s2);

    float mean2 = s2;
#pragma unroll
    for (int o = 8; o; o >>= 1) mean2 += __shfl_xor_sync(0xffffffffu, mean2, o);
    mean2 *= (1.0f / 16.0f);
    float dv2 = s2 - mean2;
    float var2 = dv2 * dv2;
#pragma unroll
    for (int o = 8; o; o >>= 1) var2 += __shfl_xor_sync(0xffffffffu, var2, o);
    var2 *= (1.0f / 16.0f);
    float t2 = dv2 * rsqrtf(var2 + 1e-5f);

    if (last) {
        if (ok) outx[grow * DM + d] = t2;
        return;
    }
    if (ok) g_x[grow * DM + d] = t2;

    float x2k[16];
#pragma unroll
    for (int k = 0; k < 16; k++) x2k[k] = __shfl_sync(0xffffffffu, t2, base + k);
    if (ok) {
        float q = 0.f, kk = 0.f, vv = 0.f;
#pragma unroll
        for (int m = 0; m < 16; m++) {
            q  = fmaf(x2k[m], swq[m * 16 + d], q);
            kk = fmaf(x2k[m], swk[m * 16 + d], kk);
            vv = fmaf(x2k[m], swv[m * 16 + d], vv);
        }
        int b = grow / S_LEN, s = grow - b * S_LEN;
        int h = d >> 1, dk = d & 1;
        int o = ((b * NH + h) * S_LEN + s) * 2 + dk;
        g_q[o] = q; g_k[o] = kk; g_v[o] = vv;
    }
}

// ---------------------------------------------------------------------------
extern "C" void kernel_launch(void* const* d_in, const int* in_sizes, int n_in,
                              void* d_out, int out_size)
{
    const float* enc  = (const float*)d_in[0];
    const float* srcw = (const float*)d_in[1];
    const float* srcb = (const float*)d_in[2];
    const float* Wq   = (const float*)d_in[3];
    const float* Wk   = (const float*)d_in[4];
    const float* Wv   = (const float*)d_in[5];
    const float* Wo   = (const float*)d_in[6];
    const float* W1   = (const float*)d_in[7];
    const float* W2   = (const float*)d_in[8];
    float* out = (float*)d_out;

    embed_kernel<<<94, 512>>>(enc, srcw, srcb, Wq, Wk, Wv);
    for (int l = 0; l < 3; l++) {
        attn_kernel<<<dim3(BATCHN * NH, YBLK), 128>>>(
            out + XELEMS + (size_t)l * (size_t)BATCHN * NH * S_LEN * S_LEN);
        int last = (l == 2);
        post_kernel<<<94, 512>>>(Wo + l * 256, W1 + l * 2048, W2 + l * 2048,
                                 last ? Wq : Wq + (l + 1) * 256,
                                 last ? Wk : Wk + (l + 1) * 256,
                                 last ? Wv : Wv + (l + 1) * 256,
                                 out, last);
    }
}

// round 4
// speedup vs baseline: 1.0807x; 1.0807x over previous
#include <cuda_runtime.h>
#include <math_constants.h>
#include <cstdint>

#define S_LEN 1500
#define BATCHN 2
#define NH 8
#define DM 16
#define DFF 128
#define NROWS (BATCHN * S_LEN)          // 3000
#define XELEMS (NROWS * DM)             // 48000
#define QPB 84                          // queries per block
#define YBLK 18                         // 17*84+72 = 1500
#define STAG_PAD 1504                   // 16B-aligned row buffer

// Scratch (no allocations allowed)
__device__ float g_x[XELEMS];
__device__ float g_q[XELEMS];           // [B,H,S,2]
__device__ float g_k[XELEMS];
__device__ float g_v[XELEMS];
__device__ float g_ctx[XELEMS];

__device__ __forceinline__ uint32_t smem_u32(const void* p) {
    uint32_t a;
    asm("{ .reg .u64 t; cvta.to.shared.u64 t, %1; cvt.u32.u64 %0, t; }"
        : "=r"(a) : "l"(p));
    return a;
}
__device__ __forceinline__ float ex2f(float x) {
    float y;
    asm("ex2.approx.f32 %0, %1;" : "=f"(y) : "f"(x));
    return y;
}

// ---------------------------------------------------------------------------
// embed + layer-0 qkv: 32 rows per 512-thread block
__global__ void __launch_bounds__(512) embed_kernel(
    const float* __restrict__ enc, const float* __restrict__ srcw,
    const float* __restrict__ srcb, const float* __restrict__ Wq,
    const float* __restrict__ Wk, const float* __restrict__ Wv)
{
    __shared__ float swq[256], swk[256], swv[256];
    int tid = threadIdx.x;
    if (tid < 256) { swq[tid] = Wq[tid]; swk[tid] = Wk[tid]; swv[tid] = Wv[tid]; }

    int r = tid >> 4, d = tid & 15;
    int grow = blockIdx.x * 32 + r;          // = b*1500 + s
    int lane = tid & 31, base = lane & 16;
    float xv = 0.f;
    if (grow < NROWS) {
        int s = grow % S_LEN;
        const float c = -0.57564627324851148f;   // -ln(10000)/16
        float dv = __expf((float)(d & ~1) * c);
        float ph = (float)s * dv;
        float pe = (d & 1) ? cosf(ph) : sinf(ph);
        xv = enc[grow] * srcw[d] + srcb[d] + pe;
        g_x[grow * DM + d] = xv;
    }
    __syncthreads();

    float xk[16];
#pragma unroll
    for (int k = 0; k < 16; k++) xk[k] = __shfl_sync(0xffffffffu, xv, base + k);
    if (grow < NROWS) {
        float q = 0.f, kk = 0.f, vv = 0.f;
#pragma unroll
        for (int m = 0; m < 16; m++) {
            q  = fmaf(xk[m], swq[m * 16 + d], q);
            kk = fmaf(xk[m], swk[m * 16 + d], kk);
            vv = fmaf(xk[m], swv[m * 16 + d], vv);
        }
        int b = grow / S_LEN, s = grow - b * S_LEN;
        int h = d >> 1, dk = d & 1;
        int o = ((b * NH + h) * S_LEN + s) * 2 + dk;
        g_q[o] = q; g_k[o] = kk; g_v[o] = vv;
    }
}

// ---------------------------------------------------------------------------
// attention: 8 warps/block, warp-per-query single pass; exp in regs; scaled
// row staged in per-warp SMEM buffer, stored via cp.async.bulk.
__global__ void __launch_bounds__(256, 2) attn_kernel(float* __restrict__ attn_out)
{
    extern __shared__ __align__(16) float smem[];
    float4* skv = (float4*)smem;                 // [1500] (k.x,k.y,v.x,v.y)
    float*  stagbase = smem + 4 * S_LEN;         // [8][STAG_PAD]

    int bh = blockIdx.x;
    int tid = threadIdx.x;
    const float2* kp = ((const float2*)g_k) + bh * S_LEN;
    const float2* vp = ((const float2*)g_v) + bh * S_LEN;
    for (int i = tid; i < S_LEN; i += 256) {
        float2 kk = kp[i], vv = vp[i];
        skv[i] = make_float4(kk.x, kk.y, vv.x, vv.y);
    }
    __syncthreads();

    int warp = tid >> 5, lane = tid & 31;
    float* stag = stagbase + warp * STAG_PAD;
    uint32_t sbuf = smem_u32(stag);
    int b = bh >> 3, h = bh & 7;
    int q0 = blockIdx.y * QPB;
    int qend = min(q0 + QPB, S_LEN);
    // fold 1/sqrt(dk) and log2(e) into q
    const float qscale = 0.70710678118654752f * 1.44269504088896341f;

    for (int q = q0 + warp; q < qend; q += 8) {
        float2 qv = ((const float2*)g_q)[bh * S_LEN + q];
        qv.x *= qscale; qv.y *= qscale;

        float4 e[12];
        float sum = 0.f, c0 = 0.f, c1 = 0.f;
#pragma unroll
        for (int i = 0; i < 12; i++) {
            int i4 = lane + 32 * i;              // covers keys 4*i4 .. 4*i4+3
            if (i4 < 375) {
                float4 kv0 = skv[4 * i4 + 0];
                float4 kv1 = skv[4 * i4 + 1];
                float4 kv2 = skv[4 * i4 + 2];
                float4 kv3 = skv[4 * i4 + 3];
                float4 A;
                A.x = ex2f(fmaf(qv.x, kv0.x, qv.y * kv0.y));
                A.y = ex2f(fmaf(qv.x, kv1.x, qv.y * kv1.y));
                A.z = ex2f(fmaf(qv.x, kv2.x, qv.y * kv2.y));
                A.w = ex2f(fmaf(qv.x, kv3.x, qv.y * kv3.y));
                sum += (A.x + A.y) + (A.z + A.w);
                c0 = fmaf(A.x, kv0.z, fmaf(A.y, kv1.z, fmaf(A.z, kv2.z, fmaf(A.w, kv3.z, c0))));
                c1 = fmaf(A.x, kv0.w, fmaf(A.y, kv1.w, fmaf(A.z, kv2.w, fmaf(A.w, kv3.w, c1))));
                e[i] = A;
            }
        }
#pragma unroll
        for (int o = 16; o; o >>= 1) {
            sum += __shfl_xor_sync(0xffffffffu, sum, o);
            c0  += __shfl_xor_sync(0xffffffffu, c0, o);
            c1  += __shfl_xor_sync(0xffffffffu, c1, o);
        }
        float rcp = 1.0f / sum;

        // previous bulk store from this warp's buffer must have drained
        if (lane == 0)
            asm volatile("cp.async.bulk.wait_group.read 0;" ::: "memory");
        __syncwarp();

        float4* srow = (float4*)stag;
#pragma unroll
        for (int i = 0; i < 12; i++) {
            int i4 = lane + 32 * i;
            if (i4 < 375) {
                float4 A = e[i];
                A.x *= rcp; A.y *= rcp; A.z *= rcp; A.w *= rcp;
                srow[i4] = A;
            }
        }
        __syncwarp();

        if (lane == 0) {
            asm volatile("fence.proxy.async.shared::cta;" ::: "memory");
            float* gdst = attn_out + ((size_t)bh * S_LEN + q) * S_LEN;
            asm volatile(
                "cp.async.bulk.global.shared::cta.bulk_group [%0], [%1], %2;"
                :: "l"(gdst), "r"(sbuf), "r"((uint32_t)(S_LEN * 4)) : "memory");
            asm volatile("cp.async.bulk.commit_group;" ::: "memory");
            int basec = (b * S_LEN + q) * DM + h * 2;
            g_ctx[basec]     = c0 * rcp;
            g_ctx[basec + 1] = c1 * rcp;
        }
    }
    if (lane == 0)
        asm volatile("cp.async.bulk.wait_group 0;" ::: "memory");
}

// ---------------------------------------------------------------------------
// post: x=LN(ctx@Wo+x); x=LN(relu(x@W1)@W2+x); then next-layer qkv (fused).
__global__ void __launch_bounds__(512) post_kernel(
    const float* __restrict__ Wo, const float* __restrict__ W1,
    const float* __restrict__ W2, const float* __restrict__ Wqn,
    const float* __restrict__ Wkn, const float* __restrict__ Wvn,
    float* __restrict__ outx, int last)
{
    __shared__ float sw1[DM * DFF];
    __shared__ float sw2[DFF * DM];
    __shared__ float swo[256];
    __shared__ float swq[256], swk[256], swv[256];
    __shared__ float sh[32][DFF];

    int tid = threadIdx.x;
    if (tid < 256) swo[tid] = Wo[tid];
    for (int i = tid; i < DM * DFF; i += 512) { sw1[i] = W1[i]; sw2[i] = W2[i]; }
    if (!last && tid < 256) { swq[tid] = Wqn[tid]; swk[tid] = Wkn[tid]; swv[tid] = Wvn[tid]; }

    int r = tid >> 4, d = tid & 15;
    int grow = blockIdx.x * 32 + r;
    int lane = tid & 31, base = lane & 16;
    bool ok = grow < NROWS;
    float xv = ok ? g_x[grow * DM + d]   : 0.f;
    float cv = ok ? g_ctx[grow * DM + d] : 0.f;
    __syncthreads();

    float s1 = xv;
#pragma unroll
    for (int k = 0; k < 16; k++) {
        float ck = __shfl_sync(0xffffffffu, cv, base + k);
        s1 = fmaf(ck, swo[k * 16 + d], s1);
    }

    float mean = s1;
#pragma unroll
    for (int o = 8; o; o >>= 1) mean += __shfl_xor_sync(0xffffffffu, mean, o);
    mean *= (1.0f / 16.0f);
    float dv = s1 - mean;
    float var = dv * dv;
#pragma unroll
    for (int o = 8; o; o >>= 1) var += __shfl_xor_sync(0xffffffffu, var, o);
    var *= (1.0f / 16.0f);
    float t = dv * rsqrtf(var + 1e-5f);

    float tk[16];
#pragma unroll
    for (int k = 0; k < 16; k++) tk[k] = __shfl_sync(0xffffffffu, t, base + k);
#pragma unroll
    for (int i = 0; i < 8; i++) {
        int j = d + 16 * i;
        float hv = 0.f;
#pragma unroll
        for (int k = 0; k < 16; k++) hv = fmaf(tk[k], sw1[k * DFF + j], hv);
        sh[r][j] = fmaxf(hv, 0.f);
    }
    __syncthreads();

    float s2 = t;
#pragma unroll
    for (int j = 0; j < DFF; j++) s2 = fmaf(sh[r][j], sw2[j * 16 + d], s2);

    float mean2 = s2;
#pragma unroll
    for (int o = 8; o; o >>= 1) mean2 += __shfl_xor_sync(0xffffffffu, mean2, o);
    mean2 *= (1.0f / 16.0f);
    float dv2 = s2 - mean2;
    float var2 = dv2 * dv2;
#pragma unroll
    for (int o = 8; o; o >>= 1) var2 += __shfl_xor_sync(0xffffffffu, var2, o);
    var2 *= (1.0f / 16.0f);
    float t2 = dv2 * rsqrtf(var2 + 1e-5f);

    if (last) {
        if (ok) outx[grow * DM + d] = t2;
        return;
    }
    if (ok) g_x[grow * DM + d] = t2;

    float x2k[16];
#pragma unroll
    for (int k = 0; k < 16; k++) x2k[k] = __shfl_sync(0xffffffffu, t2, base + k);
    if (ok) {
        float q = 0.f, kk = 0.f, vv = 0.f;
#pragma unroll
        for (int m = 0; m < 16; m++) {
            q  = fmaf(x2k[m], swq[m * 16 + d], q);
            kk = fmaf(x2k[m], swk[m * 16 + d], kk);
            vv = fmaf(x2k[m], swv[m * 16 + d], vv);
        }
        int b = grow / S_LEN, s = grow - b * S_LEN;
        int h = d >> 1, dk = d & 1;
        int o = ((b * NH + h) * S_LEN + s) * 2 + dk;
        g_q[o] = q; g_k[o] = kk; g_v[o] = vv;
    }
}

// ---------------------------------------------------------------------------
extern "C" void kernel_launch(void* const* d_in, const int* in_sizes, int n_in,
                              void* d_out, int out_size)
{
    const float* enc  = (const float*)d_in[0];
    const float* srcw = (const float*)d_in[1];
    const float* srcb = (const float*)d_in[2];
    const float* Wq   = (const float*)d_in[3];
    const float* Wk   = (const float*)d_in[4];
    const float* Wv   = (const float*)d_in[5];
    const float* Wo   = (const float*)d_in[6];
    const float* W1   = (const float*)d_in[7];
    const float* W2   = (const float*)d_in[8];
    float* out = (float*)d_out;

    const int ATTN_SMEM = (4 * S_LEN + 8 * STAG_PAD) * (int)sizeof(float); // 72128
    static int configured = 0;
    if (!configured) {
        cudaFuncSetAttribute(attn_kernel,
                             cudaFuncAttributeMaxDynamicSharedMemorySize, ATTN_SMEM);
        configured = 1;
    }

    embed_kernel<<<94, 512>>>(enc, srcw, srcb, Wq, Wk, Wv);
    for (int l = 0; l < 3; l++) {
        attn_kernel<<<dim3(BATCHN * NH, YBLK), 256, ATTN_SMEM>>>(
            out + XELEMS + (size_t)l * (size_t)BATCHN * NH * S_LEN * S_LEN);
        int last = (l == 2);
        post_kernel<<<94, 512>>>(Wo + l * 256, W1 + l * 2048, W2 + l * 2048,
                                 last ? Wq : Wq + (l + 1) * 256,
                                 last ? Wk : Wk + (l + 1) * 256,
                                 last ? Wv : Wv + (l + 1) * 256,
                                 out, last);
    }
}

// round 5
// speedup vs baseline: 2.1764x; 2.0139x over previous
#include <cuda_runtime.h>
#include <math_constants.h>
#include <cstdint>

#define S_LEN 1500
#define BATCHN 2
#define NH 8
#define DM 16
#define DFF 128
#define NROWS (BATCHN * S_LEN)          // 3000
#define XELEMS (NROWS * DM)             // 48000
#define QPB 84                          // queries per block
#define YBLK 18                         // 18*84 >= 1500
#define STAG_PAD 1504                   // 16B-aligned row buffer
#define NSTEP 47                        // ceil(1500/32)

// Scratch (no allocations allowed)
__device__ float g_x[XELEMS];
__device__ float g_q[XELEMS];           // [B,H,S,2]
__device__ float g_k[XELEMS];
__device__ float g_v[XELEMS];
__device__ float g_ctx[XELEMS];

__device__ __forceinline__ uint32_t smem_u32(const void* p) {
    uint32_t a;
    asm("{ .reg .u64 t; cvta.to.shared.u64 t, %1; cvt.u32.u64 %0, t; }"
        : "=r"(a) : "l"(p));
    return a;
}
__device__ __forceinline__ float ex2f(float x) {
    float y;
    asm("ex2.approx.f32 %0, %1;" : "=f"(y) : "f"(x));
    return y;
}

// ---------------------------------------------------------------------------
// embed + layer-0 qkv: 32 rows per 512-thread block
__global__ void __launch_bounds__(512) embed_kernel(
    const float* __restrict__ enc, const float* __restrict__ srcw,
    const float* __restrict__ srcb, const float* __restrict__ Wq,
    const float* __restrict__ Wk, const float* __restrict__ Wv)
{
    __shared__ float swq[256], swk[256], swv[256];
    int tid = threadIdx.x;
    if (tid < 256) { swq[tid] = Wq[tid]; swk[tid] = Wk[tid]; swv[tid] = Wv[tid]; }

    int r = tid >> 4, d = tid & 15;
    int grow = blockIdx.x * 32 + r;          // = b*1500 + s
    int lane = tid & 31, base = lane & 16;
    float xv = 0.f;
    if (grow < NROWS) {
        int s = grow % S_LEN;
        const float c = -0.57564627324851148f;   // -ln(10000)/16
        float dv = __expf((float)(d & ~1) * c);
        float ph = (float)s * dv;
        float pe = (d & 1) ? cosf(ph) : sinf(ph);
        xv = enc[grow] * srcw[d] + srcb[d] + pe;
        g_x[grow * DM + d] = xv;
    }
    __syncthreads();

    float xk[16];
#pragma unroll
    for (int k = 0; k < 16; k++) xk[k] = __shfl_sync(0xffffffffu, xv, base + k);
    if (grow < NROWS) {
        float q = 0.f, kk = 0.f, vv = 0.f;
#pragma unroll
        for (int m = 0; m < 16; m++) {
            q  = fmaf(xk[m], swq[m * 16 + d], q);
            kk = fmaf(xk[m], swk[m * 16 + d], kk);
            vv = fmaf(xk[m], swv[m * 16 + d], vv);
        }
        int b = grow / S_LEN, s = grow - b * S_LEN;
        int h = d >> 1, dk = d & 1;
        int o = ((b * NH + h) * S_LEN + s) * 2 + dk;
        g_q[o] = q; g_k[o] = kk; g_v[o] = vv;
    }
}

// ---------------------------------------------------------------------------
// attention: 8 warps/block, warp-per-query. Conflict-free SMEM:
// lane l handles keys l, l+32, l+64, ... (consecutive lanes -> consecutive
// 16B skv entries, consecutive 4B stag entries). Row stored via cp.async.bulk.
__global__ void __launch_bounds__(256, 2) attn_kernel(float* __restrict__ attn_out)
{
    extern __shared__ __align__(16) float smem[];
    float4* skv = (float4*)smem;                 // [1500] (k.x,k.y,v.x,v.y)
    float*  stagbase = smem + 4 * S_LEN;         // [8][STAG_PAD]

    int bh = blockIdx.x;
    int tid = threadIdx.x;
    const float2* kp = ((const float2*)g_k) + bh * S_LEN;
    const float2* vp = ((const float2*)g_v) + bh * S_LEN;
    for (int i = tid; i < S_LEN; i += 256) {
        float2 kk = kp[i], vv = vp[i];
        skv[i] = make_float4(kk.x, kk.y, vv.x, vv.y);
    }
    __syncthreads();

    int warp = tid >> 5, lane = tid & 31;
    float* stag = stagbase + warp * STAG_PAD;
    uint32_t sbuf = smem_u32(stag);
    int b = bh >> 3, h = bh & 7;
    int q0 = blockIdx.y * QPB;
    int qend = min(q0 + QPB, S_LEN);
    // fold 1/sqrt(dk) and log2(e) into q
    const float qscale = 0.70710678118654752f * 1.44269504088896341f;

    for (int q = q0 + warp; q < qend; q += 8) {
        float2 qv = ((const float2*)g_q)[bh * S_LEN + q];
        qv.x *= qscale; qv.y *= qscale;

        float e[NSTEP];
        float sum = 0.f, c0 = 0.f, c1 = 0.f;
#pragma unroll
        for (int i = 0; i < NSTEP; i++) {
            int kkey = lane + 32 * i;            // conflict-free: 16B stride
            if (kkey < S_LEN) {
                float4 kv = skv[kkey];
                float A = ex2f(fmaf(qv.x, kv.x, qv.y * kv.y));
                sum += A;
                c0 = fmaf(A, kv.z, c0);
                c1 = fmaf(A, kv.w, c1);
                e[i] = A;
            }
        }
#pragma unroll
        for (int o = 16; o; o >>= 1) {
            sum += __shfl_xor_sync(0xffffffffu, sum, o);
            c0  += __shfl_xor_sync(0xffffffffu, c0, o);
            c1  += __shfl_xor_sync(0xffffffffu, c1, o);
        }
        float rcp = 1.0f / sum;

        // previous bulk store from this warp's buffer must have drained
        if (lane == 0)
            asm volatile("cp.async.bulk.wait_group.read 0;" ::: "memory");
        __syncwarp();

#pragma unroll
        for (int i = 0; i < NSTEP; i++) {
            int kkey = lane + 32 * i;            // conflict-free STS.32
            if (kkey < S_LEN) stag[kkey] = e[i] * rcp;
        }
        __syncwarp();

        if (lane == 0) {
            asm volatile("fence.proxy.async.shared::cta;" ::: "memory");
            float* gdst = attn_out + ((size_t)bh * S_LEN + q) * S_LEN;
            asm volatile(
                "cp.async.bulk.global.shared::cta.bulk_group [%0], [%1], %2;"
                :: "l"(gdst), "r"(sbuf), "r"((uint32_t)(S_LEN * 4)) : "memory");
            asm volatile("cp.async.bulk.commit_group;" ::: "memory");
            int basec = (b * S_LEN + q) * DM + h * 2;
            g_ctx[basec]     = c0 * rcp;
            g_ctx[basec + 1] = c1 * rcp;
        }
    }
    if (lane == 0)
        asm volatile("cp.async.bulk.wait_group 0;" ::: "memory");
}

// ---------------------------------------------------------------------------
// post: x=LN(ctx@Wo+x); x=LN(relu(x@W1)@W2+x); then next-layer qkv (fused).
__global__ void __launch_bounds__(512) post_kernel(
    const float* __restrict__ Wo, const float* __restrict__ W1,
    const float* __restrict__ W2, const float* __restrict__ Wqn,
    const float* __restrict__ Wkn, const float* __restrict__ Wvn,
    float* __restrict__ outx, int last)
{
    __shared__ float sw1[DM * DFF];
    __shared__ float sw2[DFF * DM];
    __shared__ float swo[256];
    __shared__ float swq[256], swk[256], swv[256];
    __shared__ float sh[32][DFF];

    int tid = threadIdx.x;
    if (tid < 256) swo[tid] = Wo[tid];
    for (int i = tid; i < DM * DFF; i += 512) { sw1[i] = W1[i]; sw2[i] = W2[i]; }
    if (!last && tid < 256) { swq[tid] = Wqn[tid]; swk[tid] = Wkn[tid]; swv[tid] = Wvn[tid]; }

    int r = tid >> 4, d = tid & 15;
    int grow = blockIdx.x * 32 + r;
    int lane = tid & 31, base = lane & 16;
    bool ok = grow < NROWS;
    float xv = ok ? g_x[grow * DM + d]   : 0.f;
    float cv = ok ? g_ctx[grow * DM + d] : 0.f;
    __syncthreads();

    float s1 = xv;
#pragma unroll
    for (int k = 0; k < 16; k++) {
        float ck = __shfl_sync(0xffffffffu, cv, base + k);
        s1 = fmaf(ck, swo[k * 16 + d], s1);
    }

    float mean = s1;
#pragma unroll
    for (int o = 8; o; o >>= 1) mean += __shfl_xor_sync(0xffffffffu, mean, o);
    mean *= (1.0f / 16.0f);
    float dv = s1 - mean;
    float var = dv * dv;
#pragma unroll
    for (int o = 8; o; o >>= 1) var += __shfl_xor_sync(0xffffffffu, var, o);
    var *= (1.0f / 16.0f);
    float t = dv * rsqrtf(var + 1e-5f);

    float tk[16];
#pragma unroll
    for (int k = 0; k < 16; k++) tk[k] = __shfl_sync(0xffffffffu, t, base + k);
#pragma unroll
    for (int i = 0; i < 8; i++) {
        int j = d + 16 * i;
        float hv = 0.f;
#pragma unroll
        for (int k = 0; k < 16; k++) hv = fmaf(tk[k], sw1[k * DFF + j], hv);
        sh[r][j] = fmaxf(hv, 0.f);
    }
    __syncthreads();

    float s2 = t;
#pragma unroll
    for (int j = 0; j < DFF; j++) s2 = fmaf(sh[r][j], sw2[j * 16 + d], s2);

    float mean2 = s2;
#pragma unroll
    for (int o = 8; o; o >>= 1) mean2 += __shfl_xor_sync(0xffffffffu, mean2, o);
    mean2 *= (1.0f / 16.0f);
    float dv2 = s2 - mean2;
    float var2 = dv2 * dv2;
#pragma unroll
    for (int o = 8; o; o >>= 1) var2 += __shfl_xor_sync(0xffffffffu, var2, o);
    var2 *= (1.0f / 16.0f);
    float t2 = dv2 * rsqrtf(var2 + 1e-5f);

    if (last) {
        if (ok) outx[grow * DM + d] = t2;
        return;
    }
    if (ok) g_x[grow * DM + d] = t2;

    float x2k[16];
#pragma unroll
    for (int k = 0; k < 16; k++) x2k[k] = __shfl_sync(0xffffffffu, t2, base + k);
    if (ok) {
        float q = 0.f, kk = 0.f, vv = 0.f;
#pragma unroll
        for (int m = 0; m < 16; m++) {
            q  = fmaf(x2k[m], swq[m * 16 + d], q);
            kk = fmaf(x2k[m], swk[m * 16 + d], kk);
            vv = fmaf(x2k[m], swv[m * 16 + d], vv);
        }
        int b = grow / S_LEN, s = grow - b * S_LEN;
        int h = d >> 1, dk = d & 1;
        int o = ((b * NH + h) * S_LEN + s) * 2 + dk;
        g_q[o] = q; g_k[o] = kk; g_v[o] = vv;
    }
}

// ---------------------------------------------------------------------------
extern "C" void kernel_launch(void* const* d_in, const int* in_sizes, int n_in,
                              void* d_out, int out_size)
{
    const float* enc  = (const float*)d_in[0];
    const float* srcw = (const float*)d_in[1];
    const float* srcb = (const float*)d_in[2];
    const float* Wq   = (const float*)d_in[3];
    const float* Wk   = (const float*)d_in[4];
    const float* Wv   = (const float*)d_in[5];
    const float* Wo   = (const float*)d_in[6];
    const float* W1   = (const float*)d_in[7];
    const float* W2   = (const float*)d_in[8];
    float* out = (float*)d_out;

    const int ATTN_SMEM = (4 * S_LEN + 8 * STAG_PAD) * (int)sizeof(float); // 72128
    static int configured = 0;
    if (!configured) {
        cudaFuncSetAttribute(attn_kernel,
                             cudaFuncAttributeMaxDynamicSharedMemorySize, ATTN_SMEM);
        configured = 1;
    }

    embed_kernel<<<94, 512>>>(enc, srcw, srcb, Wq, Wk, Wv);
    for (int l = 0; l < 3; l++) {
        attn_kernel<<<dim3(BATCHN * NH, YBLK), 256, ATTN_SMEM>>>(
            out + XELEMS + (size_t)l * (size_t)BATCHN * NH * S_LEN * S_LEN);
        int last = (l == 2);
        post_kernel<<<94, 512>>>(Wo + l * 256, W1 + l * 2048, W2 + l * 2048,
                                 last ? Wq : Wq + (l + 1) * 256,
                                 last ? Wk : Wk + (l + 1) * 256,
                                 last ? Wv : Wv + (l + 1) * 256,
                                 out, last);
    }
}

// round 6
// speedup vs baseline: 2.5181x; 1.1570x over previous
#include <cuda_runtime.h>
#include <math_constants.h>
#include <cstdint>

#define S_LEN 1500
#define BATCHN 2
#define NH 8
#define DM 16
#define DFF 128
#define NROWS (BATCHN * S_LEN)          // 3000
#define XELEMS (NROWS * DM)             // 48000
#define QPB 84                          // queries per block (even)
#define YBLK 18                         // 18*84 >= 1500
#define STAG_PAD 1504                   // 16B-aligned row buffer
#define NSTEP 47                        // ceil(1500/32)

// Scratch (no allocations allowed)
__device__ float g_x[XELEMS];
__device__ float g_q[XELEMS];           // [B,H,S,2]
__device__ float g_k[XELEMS];
__device__ float g_v[XELEMS];
__device__ float g_ctx[XELEMS];

__device__ __forceinline__ uint32_t smem_u32(const void* p) {
    uint32_t a;
    asm("{ .reg .u64 t; cvta.to.shared.u64 t, %1; cvt.u32.u64 %0, t; }"
        : "=r"(a) : "l"(p));
    return a;
}
__device__ __forceinline__ float ex2f(float x) {
    float y;
    asm("ex2.approx.f32 %0, %1;" : "=f"(y) : "f"(x));
    return y;
}

// ---------------------------------------------------------------------------
// embed + layer-0 qkv: 32 rows per 512-thread block
__global__ void __launch_bounds__(512) embed_kernel(
    const float* __restrict__ enc, const float* __restrict__ srcw,
    const float* __restrict__ srcb, const float* __restrict__ Wq,
    const float* __restrict__ Wk, const float* __restrict__ Wv)
{
    __shared__ float swq[256], swk[256], swv[256];
    int tid = threadIdx.x;
    if (tid < 256) { swq[tid] = Wq[tid]; swk[tid] = Wk[tid]; swv[tid] = Wv[tid]; }

    int r = tid >> 4, d = tid & 15;
    int grow = blockIdx.x * 32 + r;          // = b*1500 + s
    int lane = tid & 31, base = lane & 16;
    float xv = 0.f;
    if (grow < NROWS) {
        int s = grow % S_LEN;
        const float c = -0.57564627324851148f;   // -ln(10000)/16
        float dv = __expf((float)(d & ~1) * c);
        float ph = (float)s * dv;
        float pe = (d & 1) ? cosf(ph) : sinf(ph);
        xv = enc[grow] * srcw[d] + srcb[d] + pe;
        g_x[grow * DM + d] = xv;
    }
    __syncthreads();

    float xk[16];
#pragma unroll
    for (int k = 0; k < 16; k++) xk[k] = __shfl_sync(0xffffffffu, xv, base + k);
    if (grow < NROWS) {
        float q = 0.f, kk = 0.f, vv = 0.f;
#pragma unroll
        for (int m = 0; m < 16; m++) {
            q  = fmaf(xk[m], swq[m * 16 + d], q);
            kk = fmaf(xk[m], swk[m * 16 + d], kk);
            vv = fmaf(xk[m], swv[m * 16 + d], vv);
        }
        int b = grow / S_LEN, s = grow - b * S_LEN;
        int h = d >> 1, dk = d & 1;
        int o = ((b * NH + h) * S_LEN + s) * 2 + dk;
        g_q[o] = q; g_k[o] = kk; g_v[o] = vv;
    }
}

// ---------------------------------------------------------------------------
// attention: 8 warps/block, 2 queries/warp/pass sharing each kv LDS.
// Conflict-free SMEM (lane l -> keys l+32i). Rows stored via cp.async.bulk.
__global__ void __launch_bounds__(256, 2) attn_kernel(float* __restrict__ attn_out)
{
    extern __shared__ __align__(16) float smem[];
    float4* skv = (float4*)smem;                 // [1500] (k.x,k.y,v.x,v.y)
    float*  stagbase = smem + 4 * S_LEN;         // [8][STAG_PAD]

    int bh = blockIdx.x;
    int tid = threadIdx.x;
    const float2* kp = ((const float2*)g_k) + bh * S_LEN;
    const float2* vp = ((const float2*)g_v) + bh * S_LEN;
    for (int i = tid; i < S_LEN; i += 256) {
        float2 kk = kp[i], vv = vp[i];
        skv[i] = make_float4(kk.x, kk.y, vv.x, vv.y);
    }
    __syncthreads();

    int warp = tid >> 5, lane = tid & 31;
    float* stag = stagbase + warp * STAG_PAD;
    uint32_t sbuf = smem_u32(stag);
    int b = bh >> 3, h = bh & 7;
    int p0 = (blockIdx.y * QPB) >> 1;
    int pend = min(blockIdx.y * QPB + QPB, S_LEN) >> 1;
    // fold 1/sqrt(dk) and log2(e) into q
    const float qscale = 0.70710678118654752f * 1.44269504088896341f;

    for (int p = p0 + warp; p < pend; p += 8) {
        int qa = 2 * p, qb = 2 * p + 1;
        float2 qva = ((const float2*)g_q)[bh * S_LEN + qa];
        float2 qvb = ((const float2*)g_q)[bh * S_LEN + qb];
        qva.x *= qscale; qva.y *= qscale;
        qvb.x *= qscale; qvb.y *= qscale;

        float ea[NSTEP], eb[NSTEP];
        float sa = 0.f, sb = 0.f, ca0 = 0.f, ca1 = 0.f, cb0 = 0.f, cb1 = 0.f;
#pragma unroll
        for (int i = 0; i < NSTEP; i++) {
            int kkey = lane + 32 * i;            // conflict-free: 16B stride
            if (kkey < S_LEN) {
                float4 kv = skv[kkey];
                float A = ex2f(fmaf(qva.x, kv.x, qva.y * kv.y));
                float B = ex2f(fmaf(qvb.x, kv.x, qvb.y * kv.y));
                sa += A; sb += B;
                ca0 = fmaf(A, kv.z, ca0);
                ca1 = fmaf(A, kv.w, ca1);
                cb0 = fmaf(B, kv.z, cb0);
                cb1 = fmaf(B, kv.w, cb1);
                ea[i] = A; eb[i] = B;
            }
        }
#pragma unroll
        for (int o = 16; o; o >>= 1) {
            sa  += __shfl_xor_sync(0xffffffffu, sa,  o);
            sb  += __shfl_xor_sync(0xffffffffu, sb,  o);
            ca0 += __shfl_xor_sync(0xffffffffu, ca0, o);
            ca1 += __shfl_xor_sync(0xffffffffu, ca1, o);
            cb0 += __shfl_xor_sync(0xffffffffu, cb0, o);
            cb1 += __shfl_xor_sync(0xffffffffu, cb1, o);
        }
        float ra = 1.0f / sa, rb = 1.0f / sb;

        // ---- row A ----
        if (lane == 0)
            asm volatile("cp.async.bulk.wait_group.read 0;" ::: "memory");
        __syncwarp();
#pragma unroll
        for (int i = 0; i < NSTEP; i++) {
            int kkey = lane + 32 * i;
            if (kkey < S_LEN) stag[kkey] = ea[i] * ra;
        }
        __syncwarp();
        if (lane == 0) {
            asm volatile("fence.proxy.async.shared::cta;" ::: "memory");
            float* gdst = attn_out + ((size_t)bh * S_LEN + qa) * S_LEN;
            asm volatile(
                "cp.async.bulk.global.shared::cta.bulk_group [%0], [%1], %2;"
                :: "l"(gdst), "r"(sbuf), "r"((uint32_t)(S_LEN * 4)) : "memory");
            asm volatile("cp.async.bulk.commit_group;" ::: "memory");
        }

        // ---- row B ----
        if (lane == 0)
            asm volatile("cp.async.bulk.wait_group.read 0;" ::: "memory");
        __syncwarp();
#pragma unroll
        for (int i = 0; i < NSTEP; i++) {
            int kkey = lane + 32 * i;
            if (kkey < S_LEN) stag[kkey] = eb[i] * rb;
        }
        __syncwarp();
        if (lane == 0) {
            asm volatile("fence.proxy.async.shared::cta;" ::: "memory");
            float* gdst = attn_out + ((size_t)bh * S_LEN + qb) * S_LEN;
            asm volatile(
                "cp.async.bulk.global.shared::cta.bulk_group [%0], [%1], %2;"
                :: "l"(gdst), "r"(sbuf), "r"((uint32_t)(S_LEN * 4)) : "memory");
            asm volatile("cp.async.bulk.commit_group;" ::: "memory");

            int basea = (b * S_LEN + qa) * DM + h * 2;
            int baseb = (b * S_LEN + qb) * DM + h * 2;
            g_ctx[basea]     = ca0 * ra;
            g_ctx[basea + 1] = ca1 * ra;
            g_ctx[baseb]     = cb0 * rb;
            g_ctx[baseb + 1] = cb1 * rb;
        }
    }
    if (lane == 0)
        asm volatile("cp.async.bulk.wait_group 0;" ::: "memory");
}

// ---------------------------------------------------------------------------
// post: x=LN(ctx@Wo+x); x=LN(relu(x@W1)@W2+x); then next-layer qkv (fused).
__global__ void __launch_bounds__(512) post_kernel(
    const float* __restrict__ Wo, const float* __restrict__ W1,
    const float* __restrict__ W2, const float* __restrict__ Wqn,
    const float* __restrict__ Wkn, const float* __restrict__ Wvn,
    float* __restrict__ outx, int last)
{
    __shared__ float sw1[DM * DFF];
    __shared__ float sw2[DFF * DM];
    __shared__ float swo[256];
    __shared__ float swq[256], swk[256], swv[256];
    __shared__ float sh[32][DFF];

    int tid = threadIdx.x;
    if (tid < 256) swo[tid] = Wo[tid];
    for (int i = tid; i < DM * DFF; i += 512) { sw1[i] = W1[i]; sw2[i] = W2[i]; }
    if (!last && tid < 256) { swq[tid] = Wqn[tid]; swk[tid] = Wkn[tid]; swv[tid] = Wvn[tid]; }

    int r = tid >> 4, d = tid & 15;
    int grow = blockIdx.x * 32 + r;
    int lane = tid & 31, base = lane & 16;
    bool ok = grow < NROWS;
    float xv = ok ? g_x[grow * DM + d]   : 0.f;
    float cv = ok ? g_ctx[grow * DM + d] : 0.f;
    __syncthreads();

    float s1 = xv;
#pragma unroll
    for (int k = 0; k < 16; k++) {
        float ck = __shfl_sync(0xffffffffu, cv, base + k);
        s1 = fmaf(ck, swo[k * 16 + d], s1);
    }

    float mean = s1;
#pragma unroll
    for (int o = 8; o; o >>= 1) mean += __shfl_xor_sync(0xffffffffu, mean, o);
    mean *= (1.0f / 16.0f);
    float dv = s1 - mean;
    float var = dv * dv;
#pragma unroll
    for (int o = 8; o; o >>= 1) var += __shfl_xor_sync(0xffffffffu, var, o);
    var *= (1.0f / 16.0f);
    float t = dv * rsqrtf(var + 1e-5f);

    float tk[16];
#pragma unroll
    for (int k = 0; k < 16; k++) tk[k] = __shfl_sync(0xffffffffu, t, base + k);
#pragma unroll
    for (int i = 0; i < 8; i++) {
        int j = d + 16 * i;
        float hv = 0.f;
#pragma unroll
        for (int k = 0; k < 16; k++) hv = fmaf(tk[k], sw1[k * DFF + j], hv);
        sh[r][j] = fmaxf(hv, 0.f);
    }
    __syncthreads();

    float s2 = t;
#pragma unroll
    for (int j = 0; j < DFF; j++) s2 = fmaf(sh[r][j], sw2[j * 16 + d], s2);

    float mean2 = s2;
#pragma unroll
    for (int o = 8; o; o >>= 1) mean2 += __shfl_xor_sync(0xffffffffu, mean2, o);
    mean2 *= (1.0f / 16.0f);
    float dv2 = s2 - mean2;
    float var2 = dv2 * dv2;
#pragma unroll
    for (int o = 8; o; o >>= 1) var2 += __shfl_xor_sync(0xffffffffu, var2, o);
    var2 *= (1.0f / 16.0f);
    float t2 = dv2 * rsqrtf(var2 + 1e-5f);

    if (last) {
        if (ok) outx[grow * DM + d] = t2;
        return;
    }
    if (ok) g_x[grow * DM + d] = t2;

    float x2k[16];
#pragma unroll
    for (int k = 0; k < 16; k++) x2k[k] = __shfl_sync(0xffffffffu, t2, base + k);
    if (ok) {
        float q = 0.f, kk = 0.f, vv = 0.f;
#pragma unroll
        for (int m = 0; m < 16; m++) {
            q  = fmaf(x2k[m], swq[m * 16 + d], q);
            kk = fmaf(x2k[m], swk[m * 16 + d], kk);
            vv = fmaf(x2k[m], swv[m * 16 + d], vv);
        }
        int b = grow / S_LEN, s = grow - b * S_LEN;
        int h = d >> 1, dk = d & 1;
        int o = ((b * NH + h) * S_LEN + s) * 2 + dk;
        g_q[o] = q; g_k[o] = kk; g_v[o] = vv;
    }
}

// ---------------------------------------------------------------------------
extern "C" void kernel_launch(void* const* d_in, const int* in_sizes, int n_in,
                              void* d_out, int out_size)
{
    const float* enc  = (const float*)d_in[0];
    const float* srcw = (const float*)d_in[1];
    const float* srcb = (const float*)d_in[2];
    const float* Wq   = (const float*)d_in[3];
    const float* Wk   = (const float*)d_in[4];
    const float* Wv   = (const float*)d_in[5];
    const float* Wo   = (const float*)d_in[6];
    const float* W1   = (const float*)d_in[7];
    const float* W2   = (const float*)d_in[8];
    float* out = (float*)d_out;

    const int ATTN_SMEM = (4 * S_LEN + 8 * STAG_PAD) * (int)sizeof(float); // 72128
    static int configured = 0;
    if (!configured) {
        cudaFuncSetAttribute(attn_kernel,
                             cudaFuncAttributeMaxDynamicSharedMemorySize, ATTN_SMEM);
        configured = 1;
    }

    embed_kernel<<<94, 512>>>(enc, srcw, srcb, Wq, Wk, Wv);
    for (int l = 0; l < 3; l++) {
        attn_kernel<<<dim3(BATCHN * NH, YBLK), 256, ATTN_SMEM>>>(
            out + XELEMS + (size_t)l * (size_t)BATCHN * NH * S_LEN * S_LEN);
        int last = (l == 2);
        post_kernel<<<94, 512>>>(Wo + l * 256, W1 + l * 2048, W2 + l * 2048,
                                 last ? Wq : Wq + (l + 1) * 256,
                                 last ? Wk : Wk + (l + 1) * 256,
                                 last ? Wv : Wv + (l + 1) * 256,
                                 out, last);
    }
}

// round 7
// speedup vs baseline: 2.5622x; 1.0175x over previous
#include <cuda_runtime.h>
#include <math_constants.h>
#include <cstdint>

#define S_LEN 1500
#define BATCHN 2
#define NH 8
#define DM 16
#define DFF 128
#define NROWS (BATCHN * S_LEN)          // 3000
#define XELEMS (NROWS * DM)             // 48000
#define QPB 168                         // queries per block (even)
#define YBLK 9                          // 9*168 >= 1500
#define STAG_LEN 1500                   // floats per stag buffer (6000B, 16B mult)
#define NSTEP 47                        // ceil(1500/32)

// Scratch (no allocations allowed)
__device__ float g_x[XELEMS];
__device__ float g_q[XELEMS];           // [B,H,S,2]
__device__ float g_k[XELEMS];
__device__ float g_v[XELEMS];
__device__ float g_ctx[XELEMS];

__device__ __forceinline__ uint32_t smem_u32(const void* p) {
    uint32_t a;
    asm("{ .reg .u64 t; cvta.to.shared.u64 t, %1; cvt.u32.u64 %0, t; }"
        : "=r"(a) : "l"(p));
    return a;
}
__device__ __forceinline__ float ex2f(float x) {
    float y;
    asm("ex2.approx.f32 %0, %1;" : "=f"(y) : "f"(x));
    return y;
}

// ---------------------------------------------------------------------------
// embed + layer-0 qkv: 32 rows per 512-thread block
__global__ void __launch_bounds__(512) embed_kernel(
    const float* __restrict__ enc, const float* __restrict__ srcw,
    const float* __restrict__ srcb, const float* __restrict__ Wq,
    const float* __restrict__ Wk, const float* __restrict__ Wv)
{
    __shared__ float swq[256], swk[256], swv[256];
    int tid = threadIdx.x;
    if (tid < 256) { swq[tid] = Wq[tid]; swk[tid] = Wk[tid]; swv[tid] = Wv[tid]; }

    int r = tid >> 4, d = tid & 15;
    int grow = blockIdx.x * 32 + r;          // = b*1500 + s
    int lane = tid & 31, base = lane & 16;
    float xv = 0.f;
    if (grow < NROWS) {
        int s = grow % S_LEN;
        const float c = -0.57564627324851148f;   // -ln(10000)/16
        float dv = __expf((float)(d & ~1) * c);
        float ph = (float)s * dv;
        float pe = (d & 1) ? cosf(ph) : sinf(ph);
        xv = enc[grow] * srcw[d] + srcb[d] + pe;
        g_x[grow * DM + d] = xv;
    }
    __syncthreads();

    float xk[16];
#pragma unroll
    for (int k = 0; k < 16; k++) xk[k] = __shfl_sync(0xffffffffu, xv, base + k);
    if (grow < NROWS) {
        float q = 0.f, kk = 0.f, vv = 0.f;
#pragma unroll
        for (int m = 0; m < 16; m++) {
            q  = fmaf(xk[m], swq[m * 16 + d], q);
            kk = fmaf(xk[m], swk[m * 16 + d], kk);
            vv = fmaf(xk[m], swv[m * 16 + d], vv);
        }
        int b = grow / S_LEN, s = grow - b * S_LEN;
        int h = d >> 1, dk = d & 1;
        int o = ((b * NH + h) * S_LEN + s) * 2 + dk;
        g_q[o] = q; g_k[o] = kk; g_v[o] = vv;
    }
}

// ---------------------------------------------------------------------------
// attention: 16 warps/block (1 block/SM), 2 queries/warp/pass sharing kv LDS,
// double-buffered stag per warp with wait_group.read 1 so TMA drains overlap
// the next row's staging. Conflict-free SMEM throughout.
__global__ void __launch_bounds__(512, 1) attn_kernel(float* __restrict__ attn_out)
{
    extern __shared__ __align__(16) float smem[];
    float4* skv = (float4*)smem;                 // [1500] (k.x,k.y,v.x,v.y)
    float*  stagbase = smem + 4 * S_LEN;         // [16][2][STAG_LEN]

    int bh = blockIdx.x;
    int tid = threadIdx.x;
    const float2* kp = ((const float2*)g_k) + bh * S_LEN;
    const float2* vp = ((const float2*)g_v) + bh * S_LEN;
    for (int i = tid; i < S_LEN; i += 512) {
        float2 kk = kp[i], vv = vp[i];
        skv[i] = make_float4(kk.x, kk.y, vv.x, vv.y);
    }
    __syncthreads();

    int warp = tid >> 5, lane = tid & 31;
    float* stag0 = stagbase + warp * (2 * STAG_LEN);
    float* stag1 = stag0 + STAG_LEN;
    uint32_t sbuf0 = smem_u32(stag0);
    uint32_t sbuf1 = smem_u32(stag1);
    int b = bh >> 3, h = bh & 7;
    int p0 = (blockIdx.y * QPB) >> 1;
    int pend = min(blockIdx.y * QPB + QPB, S_LEN) >> 1;
    // fold 1/sqrt(dk) and log2(e) into q
    const float qscale = 0.70710678118654752f * 1.44269504088896341f;

    for (int p = p0 + warp; p < pend; p += 16) {
        int qa = 2 * p, qb = 2 * p + 1;
        float2 qva = ((const float2*)g_q)[bh * S_LEN + qa];
        float2 qvb = ((const float2*)g_q)[bh * S_LEN + qb];
        qva.x *= qscale; qva.y *= qscale;
        qvb.x *= qscale; qvb.y *= qscale;

        float ea[NSTEP], eb[NSTEP];
        float sa = 0.f, sb = 0.f, ca0 = 0.f, ca1 = 0.f, cb0 = 0.f, cb1 = 0.f;
#pragma unroll
        for (int i = 0; i < NSTEP; i++) {
            int kkey = lane + 32 * i;            // conflict-free: 16B stride
            if (kkey < S_LEN) {
                float4 kv = skv[kkey];
                float A = ex2f(fmaf(qva.x, kv.x, qva.y * kv.y));
                float B = ex2f(fmaf(qvb.x, kv.x, qvb.y * kv.y));
                sa += A; sb += B;
                ca0 = fmaf(A, kv.z, ca0);
                ca1 = fmaf(A, kv.w, ca1);
                cb0 = fmaf(B, kv.z, cb0);
                cb1 = fmaf(B, kv.w, cb1);
                ea[i] = A; eb[i] = B;
            }
        }
#pragma unroll
        for (int o = 16; o; o >>= 1) {
            sa  += __shfl_xor_sync(0xffffffffu, sa,  o);
            sb  += __shfl_xor_sync(0xffffffffu, sb,  o);
            ca0 += __shfl_xor_sync(0xffffffffu, ca0, o);
            ca1 += __shfl_xor_sync(0xffffffffu, ca1, o);
            cb0 += __shfl_xor_sync(0xffffffffu, cb0, o);
            cb1 += __shfl_xor_sync(0xffffffffu, cb1, o);
        }
        float ra = 1.0f / sa, rb = 1.0f / sb;

        // ---- row A -> stag0 ----
        // allow one in-flight group (the one reading stag1); the group that
        // last read stag0 must have drained.
        if (lane == 0)
            asm volatile("cp.async.bulk.wait_group.read 1;" ::: "memory");
        __syncwarp();
#pragma unroll
        for (int i = 0; i < NSTEP; i++) {
            int kkey = lane + 32 * i;
            if (kkey < S_LEN) stag0[kkey] = ea[i] * ra;
        }
        __syncwarp();
        if (lane == 0) {
            asm volatile("fence.proxy.async.shared::cta;" ::: "memory");
            float* gdst = attn_out + ((size_t)bh * S_LEN + qa) * S_LEN;
            asm volatile(
                "cp.async.bulk.global.shared::cta.bulk_group [%0], [%1], %2;"
                :: "l"(gdst), "r"(sbuf0), "r"((uint32_t)(S_LEN * 4)) : "memory");
            asm volatile("cp.async.bulk.commit_group;" ::: "memory");
        }

        // ---- row B -> stag1 ----
        if (lane == 0)
            asm volatile("cp.async.bulk.wait_group.read 1;" ::: "memory");
        __syncwarp();
#pragma unroll
        for (int i = 0; i < NSTEP; i++) {
            int kkey = lane + 32 * i;
            if (kkey < S_LEN) stag1[kkey] = eb[i] * rb;
        }
        __syncwarp();
        if (lane == 0) {
            asm volatile("fence.proxy.async.shared::cta;" ::: "memory");
            float* gdst = attn_out + ((size_t)bh * S_LEN + qb) * S_LEN;
            asm volatile(
                "cp.async.bulk.global.shared::cta.bulk_group [%0], [%1], %2;"
                :: "l"(gdst), "r"(sbuf1), "r"((uint32_t)(S_LEN * 4)) : "memory");
            asm volatile("cp.async.bulk.commit_group;" ::: "memory");

            int basea = (b * S_LEN + qa) * DM + h * 2;
            int baseb = (b * S_LEN + qb) * DM + h * 2;
            g_ctx[basea]     = ca0 * ra;
            g_ctx[basea + 1] = ca1 * ra;
            g_ctx[baseb]     = cb0 * rb;
            g_ctx[baseb + 1] = cb1 * rb;
        }
    }
    if (lane == 0)
        asm volatile("cp.async.bulk.wait_group 0;" ::: "memory");
}

// ---------------------------------------------------------------------------
// post: x=LN(ctx@Wo+x); x=LN(relu(x@W1)@W2+x); then next-layer qkv (fused).
__global__ void __launch_bounds__(512) post_kernel(
    const float* __restrict__ Wo, const float* __restrict__ W1,
    const float* __restrict__ W2, const float* __restrict__ Wqn,
    const float* __restrict__ Wkn, const float* __restrict__ Wvn,
    float* __restrict__ outx, int last)
{
    __shared__ float sw1[DM * DFF];
    __shared__ float sw2[DFF * DM];
    __shared__ float swo[256];
    __shared__ float swq[256], swk[256], swv[256];
    __shared__ float sh[32][DFF];

    int tid = threadIdx.x;
    if (tid < 256) swo[tid] = Wo[tid];
    for (int i = tid; i < DM * DFF; i += 512) { sw1[i] = W1[i]; sw2[i] = W2[i]; }
    if (!last && tid < 256) { swq[tid] = Wqn[tid]; swk[tid] = Wkn[tid]; swv[tid] = Wvn[tid]; }

    int r = tid >> 4, d = tid & 15;
    int grow = blockIdx.x * 32 + r;
    int lane = tid & 31, base = lane & 16;
    bool ok = grow < NROWS;
    float xv = ok ? g_x[grow * DM + d]   : 0.f;
    float cv = ok ? g_ctx[grow * DM + d] : 0.f;
    __syncthreads();

    float s1 = xv;
#pragma unroll
    for (int k = 0; k < 16; k++) {
        float ck = __shfl_sync(0xffffffffu, cv, base + k);
        s1 = fmaf(ck, swo[k * 16 + d], s1);
    }

    float mean = s1;
#pragma unroll
    for (int o = 8; o; o >>= 1) mean += __shfl_xor_sync(0xffffffffu, mean, o);
    mean *= (1.0f / 16.0f);
    float dv = s1 - mean;
    float var = dv * dv;
#pragma unroll
    for (int o = 8; o; o >>= 1) var += __shfl_xor_sync(0xffffffffu, var, o);
    var *= (1.0f / 16.0f);
    float t = dv * rsqrtf(var + 1e-5f);

    float tk[16];
#pragma unroll
    for (int k = 0; k < 16; k++) tk[k] = __shfl_sync(0xffffffffu, t, base + k);
#pragma unroll
    for (int i = 0; i < 8; i++) {
        int j = d + 16 * i;
        float hv = 0.f;
#pragma unroll
        for (int k = 0; k < 16; k++) hv = fmaf(tk[k], sw1[k * DFF + j], hv);
        sh[r][j] = fmaxf(hv, 0.f);
    }
    __syncthreads();

    float s2 = t;
#pragma unroll
    for (int j = 0; j < DFF; j++) s2 = fmaf(sh[r][j], sw2[j * 16 + d], s2);

    float mean2 = s2;
#pragma unroll
    for (int o = 8; o; o >>= 1) mean2 += __shfl_xor_sync(0xffffffffu, mean2, o);
    mean2 *= (1.0f / 16.0f);
    float dv2 = s2 - mean2;
    float var2 = dv2 * dv2;
#pragma unroll
    for (int o = 8; o; o >>= 1) var2 += __shfl_xor_sync(0xffffffffu, var2, o);
    var2 *= (1.0f / 16.0f);
    float t2 = dv2 * rsqrtf(var2 + 1e-5f);

    if (last) {
        if (ok) outx[grow * DM + d] = t2;
        return;
    }
    if (ok) g_x[grow * DM + d] = t2;

    float x2k[16];
#pragma unroll
    for (int k = 0; k < 16; k++) x2k[k] = __shfl_sync(0xffffffffu, t2, base + k);
    if (ok) {
        float q = 0.f, kk = 0.f, vv = 0.f;
#pragma unroll
        for (int m = 0; m < 16; m++) {
            q  = fmaf(x2k[m], swq[m * 16 + d], q);
            kk = fmaf(x2k[m], swk[m * 16 + d], kk);
            vv = fmaf(x2k[m], swv[m * 16 + d], vv);
        }
        int b = grow / S_LEN, s = grow - b * S_LEN;
        int h = d >> 1, dk = d & 1;
        int o = ((b * NH + h) * S_LEN + s) * 2 + dk;
        g_q[o] = q; g_k[o] = kk; g_v[o] = vv;
    }
}

// ---------------------------------------------------------------------------
extern "C" void kernel_launch(void* const* d_in, const int* in_sizes, int n_in,
                              void* d_out, int out_size)
{
    const float* enc  = (const float*)d_in[0];
    const float* srcw = (const float*)d_in[1];
    const float* srcb = (const float*)d_in[2];
    const float* Wq   = (const float*)d_in[3];
    const float* Wk   = (const float*)d_in[4];
    const float* Wv   = (const float*)d_in[5];
    const float* Wo   = (const float*)d_in[6];
    const float* W1   = (const float*)d_in[7];
    const float* W2   = (const float*)d_in[8];
    float* out = (float*)d_out;

    const int ATTN_SMEM = (4 * S_LEN + 16 * 2 * STAG_LEN) * (int)sizeof(float); // 216000
    static int configured = 0;
    if (!configured) {
        cudaFuncSetAttribute(attn_kernel,
                             cudaFuncAttributeMaxDynamicSharedMemorySize, ATTN_SMEM);
        configured = 1;
    }

    embed_kernel<<<94, 512>>>(enc, srcw, srcb, Wq, Wk, Wv);
    for (int l = 0; l < 3; l++) {
        attn_kernel<<<dim3(BATCHN * NH, YBLK), 512, ATTN_SMEM>>>(
            out + XELEMS + (size_t)l * (size_t)BATCHN * NH * S_LEN * S_LEN);
        int last = (l == 2);
        post_kernel<<<94, 512>>>(Wo + l * 256, W1 + l * 2048, W2 + l * 2048,
                                 last ? Wq : Wq + (l + 1) * 256,
                                 last ? Wk : Wk + (l + 1) * 256,
                                 last ? Wv : Wv + (l + 1) * 256,
                                 out, last);
    }
}